// round 1
// baseline (speedup 1.0000x reference)
#include <cuda_runtime.h>
#include <math.h>

#define PH 11
#define PW 11
#define SCALEF 0.0625f
#define FH 200
#define FW 200
#define NC 256

// Warp = one (roi, channel). Lanes 0..21 = the 22 x-sample positions of a bin
// row (px = lane>>1, sx = lane&1). Loop over the 22 y-sample rows; 4 corner
// loads per lane per row span <= ~136 contiguous bytes across the warp
// (coalesced). shfl_xor(1) folds the 2x sample pair; accumulate over sy;
// even lanes write pooled bin to a per-warp smem tile; 25 lanes maxpool 3x3/s2.
__global__ __launch_bounds__(256) void roialign_maxpool_kernel(
    const float* __restrict__ feat,
    const float* __restrict__ rois,
    float* __restrict__ out)
{
    __shared__ float pooled[8][PH][PW];

    const int k    = blockIdx.x;
    const int warp = threadIdx.x >> 5;
    const int lane = threadIdx.x & 31;
    const int c    = blockIdx.y * 8 + warp;

    // Per-roi geometry (uniform across warp; broadcast loads hit L1/L2)
    const float b_f = __ldg(&rois[k * 5 + 0]);
    const float x1  = __ldg(&rois[k * 5 + 1]) * SCALEF;
    const float y1  = __ldg(&rois[k * 5 + 2]) * SCALEF;
    const float x2  = __ldg(&rois[k * 5 + 3]) * SCALEF;
    const float y2  = __ldg(&rois[k * 5 + 4]) * SCALEF;
    const int   b   = (int)b_f;

    const float roi_w = fmaxf(x2 - x1, 1.0f);
    const float roi_h = fmaxf(y2 - y1, 1.0f);
    const float bin_w = roi_w * (1.0f / PW);
    const float bin_h = roi_h * (1.0f / PH);

    const float* __restrict__ fptr = feat + ((size_t)(b * NC + c)) * (FH * FW);

    // Per-lane x-sample coordinate (fixed for the whole roi/channel)
    const int  px = lane >> 1;
    const int  sx = lane & 1;
    const bool active = (lane < 2 * PW);

    float xc = x1 + ((float)px + 0.25f + 0.5f * (float)sx) * bin_w;
    xc = fminf(fmaxf(xc, 0.0f), (float)(FW - 1));
    int   xlo = (int)floorf(xc);
    int   xhi = min(xlo + 1, FW - 1);
    float lx  = xc - (float)xlo;

    for (int py = 0; py < PH; ++py) {
        float acc = 0.0f;
#pragma unroll
        for (int sy = 0; sy < 2; ++sy) {
            // y coordinate is uniform across the warp
            float yc = y1 + ((float)py + 0.25f + 0.5f * (float)sy) * bin_h;
            yc = fminf(fmaxf(yc, 0.0f), (float)(FH - 1));
            int   ylo = (int)floorf(yc);
            int   yhi = min(ylo + 1, FH - 1);
            float ly  = yc - (float)ylo;

            float v = 0.0f;
            if (active) {
                const float* rA = fptr + ylo * FW;
                const float* rB = fptr + yhi * FW;
                float v00 = __ldg(rA + xlo);
                float v01 = __ldg(rA + xhi);
                float v10 = __ldg(rB + xlo);
                float v11 = __ldg(rB + xhi);
                float top = v00 + lx * (v01 - v00);
                float bot = v10 + lx * (v11 - v10);
                v = top + ly * (bot - top);
            }
            // fold the sx pair: lanes (2px, 2px+1) both end with the pair sum
            v += __shfl_xor_sync(0xffffffffu, v, 1);
            acc += v;
        }
        if (active && (sx == 0))
            pooled[warp][py][px] = acc * 0.25f;  // mean over 2x2 samples
    }
    __syncwarp();

    // 3x3 stride-2 maxpool over the 11x11 pooled tile -> 5x5
    if (lane < 25) {
        const int oy = lane / 5;
        const int ox = lane % 5;
        float m = -INFINITY;
#pragma unroll
        for (int dy = 0; dy < 3; ++dy)
#pragma unroll
            for (int dx = 0; dx < 3; ++dx)
                m = fmaxf(m, pooled[warp][2 * oy + dy][2 * ox + dx]);
        out[(((size_t)k * NC + c) * 5 + oy) * 5 + ox] = m;
    }
}

extern "C" void kernel_launch(void* const* d_in, const int* in_sizes, int n_in,
                              void* d_out, int out_size)
{
    const float* feat = (const float*)d_in[0];
    const float* rois = (const float*)d_in[1];
    float* out = (float*)d_out;

    const int K = in_sizes[1] / 5;  // 512 rois

    dim3 grid(K, NC / 8);   // one warp per (roi, channel); 8 channels per block
    dim3 block(256);
    roialign_maxpool_kernel<<<grid, block>>>(feat, rois, out);
}

// round 2
// speedup vs baseline: 1.5913x; 1.5913x over previous
#include <cuda_runtime.h>
#include <math.h>

#define PH 11
#define PW 11
#define SCALEF 0.0625f
#define FH 200
#define FW 200
#define NC 256
#define CPW 4          // channels per warp
#define WARPS 8        // warps per block -> 32 channels per block

// Block = one roi x 32 channels. The 22 y-sample rows (row offsets + ly) are
// computed ONCE per block into smem (they are identical for every channel of
// the roi). Each warp handles 4 channels; lanes 0..21 are the 22 x-sample
// positions (px = lane>>1, sx = lane&1). Inner loop per (py,sy): 2 LDS of
// uniform row info + per-channel {2 ptr adds, 4 LDG, 6 FFMA}. shfl fold once
// per py. 25 lanes then maxpool 3x3/s2 per channel.
__global__ __launch_bounds__(256) void roialign_maxpool_kernel(
    const float* __restrict__ feat,
    const float* __restrict__ rois,
    float* __restrict__ out)
{
    __shared__ int   s_offA[2 * PH];   // ylo * FW   (elements)
    __shared__ int   s_offB[2 * PH];   // yhi * FW
    __shared__ float s_ly[2 * PH];
    __shared__ float pooled[WARPS][CPW][PH][PW];

    const int k    = blockIdx.x;
    const int tid  = threadIdx.x;
    const int warp = tid >> 5;
    const int lane = tid & 31;

    // Per-roi geometry (uniform across block)
    const float b_f = __ldg(&rois[k * 5 + 0]);
    const float x1  = __ldg(&rois[k * 5 + 1]) * SCALEF;
    const float y1  = __ldg(&rois[k * 5 + 2]) * SCALEF;
    const float x2  = __ldg(&rois[k * 5 + 3]) * SCALEF;
    const float y2  = __ldg(&rois[k * 5 + 4]) * SCALEF;
    const int   b   = (int)b_f;

    const float bin_w = fmaxf(x2 - x1, 1.0f) * (1.0f / PW);
    const float bin_h = fmaxf(y2 - y1, 1.0f) * (1.0f / PH);

    // Precompute the 22 y-sample rows once per block (threads 0..21)
    if (tid < 2 * PH) {
        float yc = y1 + ((float)tid * 0.5f + 0.25f) * bin_h;
        yc = fminf(fmaxf(yc, 0.0f), (float)(FH - 1));
        int   ylo = (int)floorf(yc);
        int   yhi = min(ylo + 1, FH - 1);
        s_offA[tid] = ylo * FW;
        s_offB[tid] = yhi * FW;
        s_ly[tid]   = yc - (float)ylo;
    }

    // Per-lane x-sample (identical for every warp of the block)
    const int  px = lane >> 1;
    const int  sx = lane & 1;
    const bool active = (lane < 2 * PW);

    float xc = x1 + ((float)px + 0.25f + 0.5f * (float)sx) * bin_w;
    xc = fminf(fmaxf(xc, 0.0f), (float)(FW - 1));
    const int   xlo = (int)floorf(xc);
    const float lx  = xc - (float)xlo;
    const int   xd  = min(xlo + 1, FW - 1) - xlo;   // 0 or 1

    // Per-warp channel group; fold the per-lane xlo into the base pointers
    const int c0 = blockIdx.y * (WARPS * CPW) + warp * CPW;
    const float* __restrict__ fp0 = feat + ((size_t)(b * NC + c0 + 0)) * (FH * FW) + xlo;
    const float* __restrict__ fp1 = fp0 + (FH * FW);
    const float* __restrict__ fp2 = fp1 + (FH * FW);
    const float* __restrict__ fp3 = fp2 + (FH * FW);

    __syncthreads();

    for (int py = 0; py < PH; ++py) {
        float a0 = 0.f, a1 = 0.f, a2 = 0.f, a3 = 0.f;
#pragma unroll
        for (int sy = 0; sy < 2; ++sy) {
            const int   t    = 2 * py + sy;
            const int   offA = s_offA[t];
            const int   offB = s_offB[t];
            const float ly   = s_ly[t];
            const float hy   = 1.0f - ly;

            if (active) {
#pragma unroll
                for (int j = 0; j < CPW; ++j) {
                    const float* fp = (j == 0) ? fp0 : (j == 1) ? fp1 : (j == 2) ? fp2 : fp3;
                    float v00 = __ldg(fp + offA);
                    float v01 = __ldg(fp + offA + xd);
                    float v10 = __ldg(fp + offB);
                    float v11 = __ldg(fp + offB + xd);
                    float top = fmaf(lx, v01 - v00, v00);
                    float bot = fmaf(lx, v11 - v10, v10);
                    float v   = fmaf(hy, top, ly * bot);
                    if (j == 0) a0 += v;
                    else if (j == 1) a1 += v;
                    else if (j == 2) a2 += v;
                    else a3 += v;
                }
            }
        }
        // fold the sx pair once per py
        a0 += __shfl_xor_sync(0xffffffffu, a0, 1);
        a1 += __shfl_xor_sync(0xffffffffu, a1, 1);
        a2 += __shfl_xor_sync(0xffffffffu, a2, 1);
        a3 += __shfl_xor_sync(0xffffffffu, a3, 1);
        if (active && (sx == 0)) {
            pooled[warp][0][py][px] = a0 * 0.25f;
            pooled[warp][1][py][px] = a1 * 0.25f;
            pooled[warp][2][py][px] = a2 * 0.25f;
            pooled[warp][3][py][px] = a3 * 0.25f;
        }
    }
    __syncwarp();

    // 3x3 stride-2 maxpool over each 11x11 pooled tile -> 5x5
    if (lane < 25) {
        const int oy = lane / 5;
        const int ox = lane % 5;
#pragma unroll
        for (int j = 0; j < CPW; ++j) {
            float m = -INFINITY;
#pragma unroll
            for (int dy = 0; dy < 3; ++dy)
#pragma unroll
                for (int dx = 0; dx < 3; ++dx)
                    m = fmaxf(m, pooled[warp][j][2 * oy + dy][2 * ox + dx]);
            out[(((size_t)k * NC + (c0 + j)) * 5 + oy) * 5 + ox] = m;
        }
    }
}

extern "C" void kernel_launch(void* const* d_in, const int* in_sizes, int n_in,
                              void* d_out, int out_size)
{
    const float* feat = (const float*)d_in[0];
    const float* rois = (const float*)d_in[1];
    float* out = (float*)d_out;

    const int K = in_sizes[1] / 5;  // 512 rois

    dim3 grid(K, NC / (WARPS * CPW));   // (512, 8)
    dim3 block(256);
    roialign_maxpool_kernel<<<grid, block>>>(feat, rois, out);
}

// round 3
// speedup vs baseline: 1.8753x; 1.1785x over previous
#include <cuda_runtime.h>
#include <math.h>

#define PH 11
#define PW 11
#define SCALEF 0.0625f
#define FH 200
#define FW 200
#define NC 256
#define CPW 4          // channels per warp
#define WARPS 8        // warps per block -> 32 channels per block

// Block = one roi x 32 channels. 22 y-sample rows precomputed once per block
// (warp-uniform). Each warp: 4 channels; lanes 0..21 = 22 x-sample positions.
// Input ranges guarantee no boundary clamping (x2*SCALE <= 193.75 < 199), so
// xhi=xlo+1 / yhi=ylo+1 always. A register cache of the current (rowA,rowB)
// bilinear corner values exploits monotone row reuse across y-samples:
// off==cOff -> full reuse; off==cOff+FW -> shift B->A, load only B; else load
// both. Cuts scattered LDGs ~2.4x. Uniform branches never diverge.
__global__ __launch_bounds__(256) void roialign_maxpool_kernel(
    const float* __restrict__ feat,
    const float* __restrict__ rois,
    float* __restrict__ out)
{
    __shared__ int   s_off[2 * PH];    // ylo * FW
    __shared__ float s_ly[2 * PH];
    __shared__ float pooled[WARPS][CPW][PH][PW];

    const int k    = blockIdx.x;
    const int tid  = threadIdx.x;
    const int warp = tid >> 5;
    const int lane = tid & 31;

    const float x1 = __ldg(&rois[k * 5 + 1]) * SCALEF;
    const float y1 = __ldg(&rois[k * 5 + 2]) * SCALEF;
    const float x2 = __ldg(&rois[k * 5 + 3]) * SCALEF;
    const float y2 = __ldg(&rois[k * 5 + 4]) * SCALEF;
    const int   b  = (int)__ldg(&rois[k * 5 + 0]);

    const float bin_w = fmaxf(x2 - x1, 1.0f) * (1.0f / PW);
    const float bin_h = fmaxf(y2 - y1, 1.0f) * (1.0f / PH);

    // 22 y-sample rows, once per block (no clamping needed by input ranges)
    if (tid < 2 * PH) {
        float yc  = y1 + ((float)tid * 0.5f + 0.25f) * bin_h;
        int   ylo = (int)floorf(yc);
        s_off[tid] = ylo * FW;
        s_ly[tid]  = yc - (float)ylo;
    }

    // Per-lane x geometry (lanes >=22 duplicate lane 21 -> broadcast loads)
    const int  l  = min(lane, 2 * PW - 1);
    const int  px = l >> 1;
    const int  sx = l & 1;
    const bool active = (lane < 2 * PW);

    float xc = x1 + ((float)px + 0.25f + 0.5f * (float)sx) * bin_w;
    const int   xlo = (int)floorf(xc);
    const float lx  = xc - (float)xlo;
    const float hx  = 1.0f - lx;

    const int c0 = blockIdx.y * (WARPS * CPW) + warp * CPW;
    const float* __restrict__ fp0 = feat + ((size_t)(b * NC + c0)) * (FH * FW) + xlo;
    const float* __restrict__ fp1 = fp0 + (FH * FW);
    const float* __restrict__ fp2 = fp1 + (FH * FW);
    const float* __restrict__ fp3 = fp2 + (FH * FW);

    __syncthreads();

    // Row-value cache: rowA/rowB (lo,hi) per channel
    float aLo0, aHi0, aLo1, aHi1, aLo2, aHi2, aLo3, aHi3;
    float bLo0, bHi0, bLo1, bHi1, bLo2, bHi2, bLo3, bHi3;
    int   cOff = -0x40000000;
    float acc0 = 0.f, acc1 = 0.f, acc2 = 0.f, acc3 = 0.f;

    for (int t = 0; t < 2 * PH; ++t) {
        const int   off = s_off[t];
        const float ly  = s_ly[t];

        if (off != cOff) {                 // warp-uniform
            if (off == cOff + FW) {        // shift: old rowB becomes rowA
                aLo0 = bLo0; aHi0 = bHi0; aLo1 = bLo1; aHi1 = bHi1;
                aLo2 = bLo2; aHi2 = bHi2; aLo3 = bLo3; aHi3 = bHi3;
            } else {                       // fresh rowA
                aLo0 = __ldg(fp0 + off);  aHi0 = __ldg(fp0 + off + 1);
                aLo1 = __ldg(fp1 + off);  aHi1 = __ldg(fp1 + off + 1);
                aLo2 = __ldg(fp2 + off);  aHi2 = __ldg(fp2 + off + 1);
                aLo3 = __ldg(fp3 + off);  aHi3 = __ldg(fp3 + off + 1);
            }
            const int offB = off + FW;     // rowB always next row (no clamp)
            bLo0 = __ldg(fp0 + offB);  bHi0 = __ldg(fp0 + offB + 1);
            bLo1 = __ldg(fp1 + offB);  bHi1 = __ldg(fp1 + offB + 1);
            bLo2 = __ldg(fp2 + offB);  bHi2 = __ldg(fp2 + offB + 1);
            bLo3 = __ldg(fp3 + offB);  bHi3 = __ldg(fp3 + offB + 1);
            cOff = off;
        }

        const float hy  = 1.0f - ly;
        const float w00 = hy * hx, w01 = hy * lx;
        const float w10 = ly * hx, w11 = ly * lx;

        float v0 = fmaf(w00, aLo0, fmaf(w01, aHi0, fmaf(w10, bLo0, w11 * bHi0)));
        float v1 = fmaf(w00, aLo1, fmaf(w01, aHi1, fmaf(w10, bLo1, w11 * bHi1)));
        float v2 = fmaf(w00, aLo2, fmaf(w01, aHi2, fmaf(w10, bLo2, w11 * bHi2)));
        float v3 = fmaf(w00, aLo3, fmaf(w01, aHi3, fmaf(w10, bLo3, w11 * bHi3)));

        if ((t & 1) == 0) {
            acc0 = v0; acc1 = v1; acc2 = v2; acc3 = v3;
        } else {
            acc0 += v0; acc1 += v1; acc2 += v2; acc3 += v3;
            // fold the sx pair; even lanes hold the bin mean
            acc0 += __shfl_xor_sync(0xffffffffu, acc0, 1);
            acc1 += __shfl_xor_sync(0xffffffffu, acc1, 1);
            acc2 += __shfl_xor_sync(0xffffffffu, acc2, 1);
            acc3 += __shfl_xor_sync(0xffffffffu, acc3, 1);
            const int py = t >> 1;
            if (active && (sx == 0)) {
                pooled[warp][0][py][px] = acc0 * 0.25f;
                pooled[warp][1][py][px] = acc1 * 0.25f;
                pooled[warp][2][py][px] = acc2 * 0.25f;
                pooled[warp][3][py][px] = acc3 * 0.25f;
            }
        }
    }
    __syncwarp();

    // 3x3 stride-2 maxpool over each 11x11 pooled tile -> 5x5
    if (lane < 25) {
        const int oy = lane / 5;
        const int ox = lane % 5;
#pragma unroll
        for (int j = 0; j < CPW; ++j) {
            float m = -INFINITY;
#pragma unroll
            for (int dy = 0; dy < 3; ++dy)
#pragma unroll
                for (int dx = 0; dx < 3; ++dx)
                    m = fmaxf(m, pooled[warp][j][2 * oy + dy][2 * ox + dx]);
            out[(((size_t)k * NC + (c0 + j)) * 5 + oy) * 5 + ox] = m;
        }
    }
}

extern "C" void kernel_launch(void* const* d_in, const int* in_sizes, int n_in,
                              void* d_out, int out_size)
{
    const float* feat = (const float*)d_in[0];
    const float* rois = (const float*)d_in[1];
    float* out = (float*)d_out;

    const int K = in_sizes[1] / 5;  // 512 rois

    dim3 grid(K, NC / (WARPS * CPW));   // (512, 8)
    dim3 block(256);
    roialign_maxpool_kernel<<<grid, block>>>(feat, rois, out);
}

// round 5
// speedup vs baseline: 2.2439x; 1.1965x over previous
#include <cuda_runtime.h>
#include <math.h>

#define PH 11
#define PW 11
#define SCALEF 0.0625f
#define FH 200
#define FW 200
#define NC 256
#define CH_STRIDE (FH * FW)   // 40000 elements
#define CPW 4
#define WARPS 8

// Block = one roi x 32 channels; warp = 4 channels; lanes 0..21 = 22 x-samples.
// Register cache holds the X-INTERPOLATED value of rowA/rowB per channel
// (lx is loop-invariant per lane), so the steady-state iteration is just
// 2 FMA/channel. Monotone row reuse: off==cOff -> full reuse; off==cOff+FW ->
// shift rB->rA + load rowB only. All loads use ONE base pointer per row
// transition with compile-time immediate offsets (ch stride 160000B < 24-bit).
__global__ __launch_bounds__(256) void roialign_maxpool_kernel(
    const float* __restrict__ feat,
    const float* __restrict__ rois,
    float* __restrict__ out)
{
    __shared__ int   s_off[2 * PH];
    __shared__ float s_ly[2 * PH];
    __shared__ float pooled[WARPS][CPW][PH][PW];

    const int k    = blockIdx.x;
    const int tid  = threadIdx.x;
    const int warp = tid >> 5;
    const int lane = tid & 31;

    const float x1 = __ldg(&rois[k * 5 + 1]) * SCALEF;
    const float y1 = __ldg(&rois[k * 5 + 2]) * SCALEF;
    const float x2 = __ldg(&rois[k * 5 + 3]) * SCALEF;
    const float y2 = __ldg(&rois[k * 5 + 4]) * SCALEF;
    const int   b  = (int)__ldg(&rois[k * 5 + 0]);

    const float bin_w = fmaxf(x2 - x1, 1.0f) * (1.0f / PW);
    const float bin_h = fmaxf(y2 - y1, 1.0f) * (1.0f / PH);

    // 22 y-sample rows once per block (input ranges guarantee no clamping)
    if (tid < 2 * PH) {
        float yc  = y1 + ((float)tid * 0.5f + 0.25f) * bin_h;
        int   ylo = (int)floorf(yc);
        s_off[tid] = ylo * FW;
        s_ly[tid]  = yc - (float)ylo;
    }

    // Per-lane x geometry (lanes >=22 duplicate lane 21 -> broadcast loads)
    const int  l  = min(lane, 2 * PW - 1);
    const int  px = l >> 1;
    const int  sx = l & 1;
    const bool active = (lane < 2 * PW);

    float xc = x1 + ((float)px + 0.25f + 0.5f * (float)sx) * bin_w;
    const int   xlo = (int)floorf(xc);
    const float lx  = xc - (float)xlo;
    const float hx  = 1.0f - lx;

    const int c0 = blockIdx.y * (WARPS * CPW) + warp * CPW;
    const float* __restrict__ fbase =
        feat + ((size_t)(b * NC + c0)) * CH_STRIDE + xlo;

    __syncthreads();

    // X-interpolated row cache (rowA, rowB) per channel
    float rA0, rA1, rA2, rA3;
    float rB0, rB1, rB2, rB3;
    int   cOff = -0x40000000;
    float acc0 = 0.f, acc1 = 0.f, acc2 = 0.f, acc3 = 0.f;

    for (int t = 0; t < 2 * PH; ++t) {
        const int   off = s_off[t];
        const float ly  = s_ly[t];

        if (off != cOff) {                       // warp-uniform branch
            const float* __restrict__ p = fbase + off;   // single base; all
                                                         // offsets immediate
            if (off == cOff + FW) {              // shift: rowB becomes rowA
                rA0 = rB0; rA1 = rB1; rA2 = rB2; rA3 = rB3;
            } else {                             // fresh rowA
                rA0 = fmaf(lx, __ldg(p + 0 * CH_STRIDE + 1), hx * __ldg(p + 0 * CH_STRIDE));
                rA1 = fmaf(lx, __ldg(p + 1 * CH_STRIDE + 1), hx * __ldg(p + 1 * CH_STRIDE));
                rA2 = fmaf(lx, __ldg(p + 2 * CH_STRIDE + 1), hx * __ldg(p + 2 * CH_STRIDE));
                rA3 = fmaf(lx, __ldg(p + 3 * CH_STRIDE + 1), hx * __ldg(p + 3 * CH_STRIDE));
            }
            rB0 = fmaf(lx, __ldg(p + 0 * CH_STRIDE + FW + 1), hx * __ldg(p + 0 * CH_STRIDE + FW));
            rB1 = fmaf(lx, __ldg(p + 1 * CH_STRIDE + FW + 1), hx * __ldg(p + 1 * CH_STRIDE + FW));
            rB2 = fmaf(lx, __ldg(p + 2 * CH_STRIDE + FW + 1), hx * __ldg(p + 2 * CH_STRIDE + FW));
            rB3 = fmaf(lx, __ldg(p + 3 * CH_STRIDE + FW + 1), hx * __ldg(p + 3 * CH_STRIDE + FW));
            cOff = off;
        }

        // y-interp: 2 ops per channel
        float v0 = fmaf(ly, rB0 - rA0, rA0);
        float v1 = fmaf(ly, rB1 - rA1, rA1);
        float v2 = fmaf(ly, rB2 - rA2, rA2);
        float v3 = fmaf(ly, rB3 - rA3, rA3);

        if ((t & 1) == 0) {
            acc0 = v0; acc1 = v1; acc2 = v2; acc3 = v3;
        } else {
            acc0 += v0; acc1 += v1; acc2 += v2; acc3 += v3;
            acc0 += __shfl_xor_sync(0xffffffffu, acc0, 1);
            acc1 += __shfl_xor_sync(0xffffffffu, acc1, 1);
            acc2 += __shfl_xor_sync(0xffffffffu, acc2, 1);
            acc3 += __shfl_xor_sync(0xffffffffu, acc3, 1);
            const int py = t >> 1;
            if (active && (sx == 0)) {
                pooled[warp][0][py][px] = acc0 * 0.25f;
                pooled[warp][1][py][px] = acc1 * 0.25f;
                pooled[warp][2][py][px] = acc2 * 0.25f;
                pooled[warp][3][py][px] = acc3 * 0.25f;
            }
        }
    }
    __syncwarp();

    // 3x3 stride-2 maxpool over each 11x11 pooled tile -> 5x5
    if (lane < 25) {
        const int oy = lane / 5;
        const int ox = lane % 5;
#pragma unroll
        for (int j = 0; j < CPW; ++j) {
            float m = -INFINITY;
#pragma unroll
            for (int dy = 0; dy < 3; ++dy)
#pragma unroll
                for (int dx = 0; dx < 3; ++dx)
                    m = fmaxf(m, pooled[warp][j][2 * oy + dy][2 * ox + dx]);
            out[(((size_t)k * NC + (c0 + j)) * 5 + oy) * 5 + ox] = m;
        }
    }
}

extern "C" void kernel_launch(void* const* d_in, const int* in_sizes, int n_in,
                              void* d_out, int out_size)
{
    const float* feat = (const float*)d_in[0];
    const float* rois = (const float*)d_in[1];
    float* out = (float*)d_out;

    const int K = in_sizes[1] / 5;  // 512 rois

    dim3 grid(K, NC / (WARPS * CPW));   // (512, 8)
    dim3 block(256);
    roialign_maxpool_kernel<<<grid, block>>>(feat, rois, out);
}